// round 10
// baseline (speedup 1.0000x reference)
#include <cuda_runtime.h>
#include <cuda_bf16.h>
#include <cstdint>

#define N_NODES 100000
#define N_EDGES 1600000
#define TM 128
#define NBLK ((N_NODES + TM - 1) / TM)
#define THREADS 512
#define NPERS 148     // persistent CTAs (~1 per SM)
#define LDK 136       // padded K stride (odd 16B stride -> conflict-free frag loads)

// ---- SMEM byte offsets (persistent layout: A + B1 + B2 resident together) ----
#define OFF_B1HI 0            // 34816 each  [128][136] bf16
#define OFF_B1LO 34816
#define OFF_B2HI 69632
#define OFF_B2LO 104448
#define OFF_AHI  139264
#define OFF_ALO  174080
#define OFF_MEA  208896       // [128][4] fp32 (col 3 = fixup scratch)
#define OFF_W1C  210944       // [3][128] fp32
#define OFF_B1   212480       // [128] fp32
#define OFF_B2   212992       // [128] fp32
#define OFF_ZB   213504       // [4] uint32 zero-degree ballots
#define SMEM_TOTAL 213536

// ---- global scratch ----
// NOTE: g_agg relies on (a) zero-initialization of __device__ globals for the
// first launch, (b) consume-and-clear inside fused_kernel for every
// subsequent launch/replay. Every complete execution leaves it all-zero.
__device__ float4 g_agg[N_NODES];                      // sum_ea0..2, count
__device__ __align__(16) __nv_bfloat16 g_B1hi[128 * LDK];  // [n][k] = Wsum[k][n]
__device__ __align__(16) __nv_bfloat16 g_B1lo[128 * LDK];
__device__ __align__(16) __nv_bfloat16 g_B2hi[128 * LDK];  // [n][k] = W2[k][n]
__device__ __align__(16) __nv_bfloat16 g_B2lo[128 * LDK];
__device__ int g_idx64;

__device__ __forceinline__ uint32_t pack_bf(float a, float b) {
    __nv_bfloat162 t = __floats2bfloat162_rn(a, b);
    return *(uint32_t*)&t;
}
__device__ __forceinline__ float bf_resid(float v) {
    return v - __bfloat162float(__float2bfloat16_rn(v));
}
__device__ __forceinline__ void mma_bf16(float* c, const uint32_t* a, const uint32_t* b) {
    asm volatile(
        "mma.sync.aligned.m16n8k16.row.col.f32.bf16.bf16.f32 "
        "{%0,%1,%2,%3}, {%4,%5,%6,%7}, {%8,%9}, {%0,%1,%2,%3};"
        : "+f"(c[0]), "+f"(c[1]), "+f"(c[2]), "+f"(c[3])
        : "r"(a[0]), "r"(a[1]), "r"(a[2]), "r"(a[3]), "r"(b[0]), "r"(b[1]));
}
__device__ __forceinline__ void red_v4(float4* p, float a, float b, float c, float d) {
    asm volatile("red.global.add.v4.f32 [%0], {%1, %2, %3, %4};"
                 :: "l"(p), "f"(a), "f"(b), "f"(c), "f"(d) : "memory");
}

// ---------------------------------------------------------------------------
// prep: build bf16 hi/lo transposed weight images, detect idx dtype
// (g_agg zeroing removed: consume-and-clear in fused_kernel maintains it)
// ---------------------------------------------------------------------------
__global__ void prep_kernel(const int* __restrict__ ei32,
                            const float* __restrict__ W1,
                            const float* __restrict__ W2) {
    int tid = blockIdx.x * blockDim.x + threadIdx.x;
    int stride = gridDim.x * blockDim.x;
    for (int i = tid; i < 128 * 128; i += stride) {
        int n = i >> 7, k = i & 127;
        float v = W1[k * 128 + n] + W1[(128 + k) * 128 + n];   // Wsum^T
        __nv_bfloat16 h = __float2bfloat16_rn(v);
        g_B1hi[n * LDK + k] = h;
        g_B1lo[n * LDK + k] = __float2bfloat16_rn(v - __bfloat162float(h));
        float w = W2[k * 128 + n];                              // W2^T
        __nv_bfloat16 h2 = __float2bfloat16_rn(w);
        g_B2hi[n * LDK + k] = h2;
        g_B2lo[n * LDK + k] = __float2bfloat16_rn(w - __bfloat162float(h2));
    }
    // zero pad columns
    for (int i = tid; i < 128 * (LDK - 128); i += stride) {
        int n = i / (LDK - 128), k = 128 + i % (LDK - 128);
        g_B1hi[n * LDK + k] = __float2bfloat16_rn(0.f);
        g_B1lo[n * LDK + k] = __float2bfloat16_rn(0.f);
        g_B2hi[n * LDK + k] = __float2bfloat16_rn(0.f);
        g_B2lo[n * LDK + k] = __float2bfloat16_rn(0.f);
    }
    if (tid == 0) {
        g_idx64 = ((ei32[1] | ei32[3] | ei32[5] | ei32[7]) == 0) ? 1 : 0;
    }
}

// ---------------------------------------------------------------------------
// scatter: 4 edges/thread, vectorized loads, 4x red.global.add.v4.f32
// ---------------------------------------------------------------------------
__global__ void scatter_kernel(const int* __restrict__ ei32, const float* __restrict__ ea) {
    int e0 = (blockIdx.x * blockDim.x + threadIdx.x) * 4;
    if (e0 >= N_EDGES) return;   // N_EDGES % 4 == 0, so full quads only
    int s0, s1, s2, s3;
    if (g_idx64) {
        const int4* p = (const int4*)(ei32 + 2 * (N_EDGES + e0));
        int4 a = p[0], b = p[1];
        s0 = a.x; s1 = a.z; s2 = b.x; s3 = b.z;   // low words of 4 int64
    } else {
        int4 a = *(const int4*)(ei32 + N_EDGES + e0);
        s0 = a.x; s1 = a.y; s2 = a.z; s3 = a.w;
    }
    const float4* q = (const float4*)(ea + (size_t)e0 * 3);
    float4 q0 = q[0], q1 = q[1], q2 = q[2];
    red_v4(&g_agg[s0], q0.x, q0.y, q0.z, 1.0f);
    red_v4(&g_agg[s1], q0.w, q1.x, q1.y, 1.0f);
    red_v4(&g_agg[s2], q1.z, q1.w, q2.x, 1.0f);
    red_v4(&g_agg[s3], q2.y, q2.z, q2.w, 1.0f);
}

// ---------------------------------------------------------------------------
// fused (persistent, 512 thr, 32x32 warp tiles): B1+B2 resident; inline fixup
// ---------------------------------------------------------------------------
__global__ __launch_bounds__(THREADS, 1)
void fused_kernel(const float* __restrict__ x,
                  const float* __restrict__ W1,
                  const float* __restrict__ b1g,
                  const float* __restrict__ W2,
                  const float* __restrict__ b2g,
                  float* __restrict__ out) {
    extern __shared__ char smem[];
    __nv_bfloat16* sB1hi = (__nv_bfloat16*)(smem + OFF_B1HI);
    __nv_bfloat16* sB1lo = (__nv_bfloat16*)(smem + OFF_B1LO);
    __nv_bfloat16* sB2hi = (__nv_bfloat16*)(smem + OFF_B2HI);
    __nv_bfloat16* sB2lo = (__nv_bfloat16*)(smem + OFF_B2LO);
    __nv_bfloat16* sAhi  = (__nv_bfloat16*)(smem + OFF_AHI);
    __nv_bfloat16* sAlo  = (__nv_bfloat16*)(smem + OFF_ALO);
    float* sMea = (float*)(smem + OFF_MEA);
    float* sW1c = (float*)(smem + OFF_W1C);
    float* sB1  = (float*)(smem + OFF_B1);
    float* sB2  = (float*)(smem + OFF_B2);
    unsigned* sZb = (unsigned*)(smem + OFF_ZB);

    const int tid = threadIdx.x, wid = tid >> 5, lane = tid & 31;
    const int gID = lane >> 2, tIG = lane & 3;
    const int wr = (wid & 3) * 32;      // warp row base (4 groups x 32 rows)
    const int wc = (wid >> 2) * 32;     // warp col base (4 groups x 32 cols)

    // ---- one-time: biases, W1c, all 4 weight images ----
    if (tid < 128) { sB1[tid] = b1g[tid]; sB2[tid] = b2g[tid]; }
    for (int i = tid; i < 3 * 128; i += THREADS) sW1c[i] = W1[256 * 128 + i];
    {
        const uint4* s1 = (const uint4*)g_B1hi;
        const uint4* s2 = (const uint4*)g_B1lo;
        const uint4* s3 = (const uint4*)g_B2hi;
        const uint4* s4 = (const uint4*)g_B2lo;
        uint4* d1 = (uint4*)sB1hi;
        uint4* d2 = (uint4*)sB1lo;
        uint4* d3 = (uint4*)sB2hi;
        uint4* d4 = (uint4*)sB2lo;
        for (int i = tid; i < 128 * LDK * 2 / 16; i += THREADS) {
            d1[i] = s1[i]; d2[i] = s2[i]; d3[i] = s3[i]; d4[i] = s4[i];
        }
    }

#define MMA_LAYER(SBH, SBL)                                                     \
    _Pragma("unroll")                                                           \
    for (int ks = 0; ks < 8; ks++) {                                            \
        const int k0 = ks * 16 + tIG * 2;                                       \
        uint32_t aH[2][4], aL[2][4], bH[4][2], bL[4][2];                        \
        _Pragma("unroll")                                                       \
        for (int ma = 0; ma < 2; ma++) {                                        \
            int r = wr + ma * 16 + gID;                                         \
            aH[ma][0] = *(const uint32_t*)(sAhi + r * LDK + k0);                \
            aH[ma][1] = *(const uint32_t*)(sAhi + (r + 8) * LDK + k0);          \
            aH[ma][2] = *(const uint32_t*)(sAhi + r * LDK + k0 + 8);            \
            aH[ma][3] = *(const uint32_t*)(sAhi + (r + 8) * LDK + k0 + 8);      \
            aL[ma][0] = *(const uint32_t*)(sAlo + r * LDK + k0);                \
            aL[ma][1] = *(const uint32_t*)(sAlo + (r + 8) * LDK + k0);          \
            aL[ma][2] = *(const uint32_t*)(sAlo + r * LDK + k0 + 8);            \
            aL[ma][3] = *(const uint32_t*)(sAlo + (r + 8) * LDK + k0 + 8);      \
        }                                                                       \
        _Pragma("unroll")                                                       \
        for (int na = 0; na < 4; na++) {                                        \
            int n = wc + na * 8 + gID;                                          \
            bH[na][0] = *(const uint32_t*)((SBH) + n * LDK + k0);               \
            bH[na][1] = *(const uint32_t*)((SBH) + n * LDK + k0 + 8);           \
            bL[na][0] = *(const uint32_t*)((SBL) + n * LDK + k0);               \
            bL[na][1] = *(const uint32_t*)((SBL) + n * LDK + k0 + 8);           \
        }                                                                       \
        _Pragma("unroll")                                                       \
        for (int ma = 0; ma < 2; ma++)                                          \
            _Pragma("unroll")                                                   \
            for (int na = 0; na < 4; na++) {                                    \
                mma_bf16(acc[ma][na], aH[ma], bH[na]);                          \
                mma_bf16(acc[ma][na], aL[ma], bH[na]);                          \
                mma_bf16(acc[ma][na], aH[ma], bL[na]);                          \
            }                                                                   \
    }

    for (int t = blockIdx.x; t < NBLK; t += gridDim.x) {
        const int node0 = t * TM;
        __syncthreads();   // one-time loads visible; sZb/sMea safe to overwrite

        // ---- mea + zero-degree ballot + consume-and-clear g_agg ----
        if (tid < TM) {
            int g = node0 + tid;
            float4 a = make_float4(0.f, 0.f, 0.f, 1.f);
            if (g < N_NODES) {
                a = g_agg[g];
                g_agg[g] = make_float4(0.f, 0.f, 0.f, 0.f);   // reset for next launch
            }
            unsigned zb = __ballot_sync(0xffffffffu, (g < N_NODES) && (a.w == 0.f));
            if (lane == 0) sZb[wid] = zb;
            float inv = 1.0f / fmaxf(a.w, 1.0f);
            sMea[tid * 4 + 0] = a.x * inv;
            sMea[tid * 4 + 1] = a.y * inv;
            sMea[tid * 4 + 2] = a.z * inv;
        }

        // ---- x -> sA hi/lo ----
        const float4* x4 = (const float4*)x;
        for (int idx = tid; idx < TM * 32; idx += THREADS) {
            int r = idx >> 5, kq = idx & 31, g = node0 + r;
            float4 v = make_float4(0.f, 0.f, 0.f, 0.f);
            if (g < N_NODES) v = x4[g * 32 + kq];
            int o = r * LDK + kq * 4;
            *(uint32_t*)(sAhi + o)     = pack_bf(v.x, v.y);
            *(uint32_t*)(sAhi + o + 2) = pack_bf(v.z, v.w);
            *(uint32_t*)(sAlo + o)     = pack_bf(bf_resid(v.x), bf_resid(v.y));
            *(uint32_t*)(sAlo + o + 2) = pack_bf(bf_resid(v.z), bf_resid(v.w));
        }
        __syncthreads();

        float acc[2][4][4];
#pragma unroll
        for (int ma = 0; ma < 2; ma++)
#pragma unroll
            for (int na = 0; na < 4; na++)
#pragma unroll
                for (int c = 0; c < 4; c++) acc[ma][na][c] = 0.f;

        MMA_LAYER(sB1hi, sB1lo)
        __syncthreads();   // all reads of sA done before epilogue1 overwrites it

        // ---- epilogue1: h = relu(acc + b1 + mea@W1c) -> sA hi/lo; reset acc ----
#pragma unroll
        for (int ma = 0; ma < 2; ma++) {
            int r0 = wr + ma * 16 + gID;
            float m00 = sMea[r0 * 4], m01 = sMea[r0 * 4 + 1], m02 = sMea[r0 * 4 + 2];
            int r1 = r0 + 8;
            float m10 = sMea[r1 * 4], m11 = sMea[r1 * 4 + 1], m12 = sMea[r1 * 4 + 2];
#pragma unroll
            for (int na = 0; na < 4; na++) {
                int c0 = wc + na * 8 + tIG * 2;
                float e0 = sB1[c0]     + m00 * sW1c[c0]     + m01 * sW1c[128 + c0]     + m02 * sW1c[256 + c0];
                float e1 = sB1[c0 + 1] + m00 * sW1c[c0 + 1] + m01 * sW1c[128 + c0 + 1] + m02 * sW1c[256 + c0 + 1];
                float f0 = sB1[c0]     + m10 * sW1c[c0]     + m11 * sW1c[128 + c0]     + m12 * sW1c[256 + c0];
                float f1 = sB1[c0 + 1] + m10 * sW1c[c0 + 1] + m11 * sW1c[128 + c0 + 1] + m12 * sW1c[256 + c0 + 1];
                float v0 = fmaxf(acc[ma][na][0] + e0, 0.f);
                float v1 = fmaxf(acc[ma][na][1] + e1, 0.f);
                float v2 = fmaxf(acc[ma][na][2] + f0, 0.f);
                float v3 = fmaxf(acc[ma][na][3] + f1, 0.f);
                *(uint32_t*)(sAhi + r0 * LDK + c0) = pack_bf(v0, v1);
                *(uint32_t*)(sAlo + r0 * LDK + c0) = pack_bf(bf_resid(v0), bf_resid(v1));
                *(uint32_t*)(sAhi + r1 * LDK + c0) = pack_bf(v2, v3);
                *(uint32_t*)(sAlo + r1 * LDK + c0) = pack_bf(bf_resid(v2), bf_resid(v3));
#pragma unroll
                for (int c = 0; c < 4; c++) acc[ma][na][c] = 0.f;
            }
        }
        __syncthreads();

        MMA_LAYER(sB2hi, sB2lo)

        // ---- epilogue2: out = acc + b2 (direct global stores, 8B each) ----
#pragma unroll
        for (int ma = 0; ma < 2; ma++) {
            int r0 = wr + ma * 16 + gID;
            int g0 = node0 + r0, g1 = g0 + 8;
#pragma unroll
            for (int na = 0; na < 4; na++) {
                int c0 = wc + na * 8 + tIG * 2;
                if (g0 < N_NODES) {
                    float2 v = make_float2(acc[ma][na][0] + sB2[c0], acc[ma][na][1] + sB2[c0 + 1]);
                    *(float2*)(out + (size_t)g0 * 128 + c0) = v;
                }
                if (g1 < N_NODES) {
                    float2 v = make_float2(acc[ma][na][2] + sB2[c0], acc[ma][na][3] + sB2[c0 + 1]);
                    *(float2*)(out + (size_t)g1 * 128 + c0) = v;
                }
            }
        }
        __syncthreads();   // orders epi2 stores + sA reads before fixup / next iter

        // ---- inline fixup: exact fp32 recompute for zero-degree nodes ----
        {
            unsigned z0 = sZb[0], z1 = sZb[1], z2 = sZb[2], z3 = sZb[3];
            if (z0 | z1 | z2 | z3) {
#pragma unroll 1
                for (int ws = 0; ws < 4; ws++) {
                    unsigned m = sZb[ws];
                    while (m) {
                        int b = __ffs(m) - 1;
                        m &= m - 1;
                        int n = node0 + ws * 32 + b;
                        if (tid < 128) {
                            float a1 = sB1[tid];
                            for (int k = 0; k < 128; k++)
                                a1 = fmaf(x[(size_t)n * 128 + k], W1[k * 128 + tid], a1);
                            sMea[tid * 4 + 3] = fmaxf(a1, 0.f);
                        }
                        __syncthreads();
                        if (tid < 128) {
                            float a2 = sB2[tid];
                            for (int k = 0; k < 128; k++)
                                a2 = fmaf(sMea[k * 4 + 3], W2[k * 128 + tid], a2);
                            out[(size_t)n * 128 + tid] = a2;
                        }
                        __syncthreads();
                    }
                }
            }
        }
    }
#undef MMA_LAYER
}

// ---------------------------------------------------------------------------
extern "C" void kernel_launch(void* const* d_in, const int* in_sizes, int n_in,
                              void* d_out, int out_size) {
    const float* x    = (const float*)d_in[0];
    const int*   ei32 = (const int*)d_in[1];
    const float* ea   = (const float*)d_in[2];
    const float* W1   = (const float*)d_in[5];
    const float* b1   = (const float*)d_in[6];
    const float* W2   = (const float*)d_in[7];
    const float* b2   = (const float*)d_in[8];
    float* out = (float*)d_out;

    cudaFuncSetAttribute(fused_kernel, cudaFuncAttributeMaxDynamicSharedMemorySize, SMEM_TOTAL);

    prep_kernel<<<64, 256>>>(ei32, W1, W2);
    scatter_kernel<<<(N_EDGES / 4 + 255) / 256, 256>>>(ei32, ea);
    fused_kernel<<<NPERS, THREADS, SMEM_TOTAL>>>(x, W1, b1, W2, b2, out);
}

// round 11
// speedup vs baseline: 1.0589x; 1.0589x over previous
#include <cuda_runtime.h>
#include <cuda_bf16.h>
#include <cstdint>

#define N_NODES 100000
#define N_EDGES 1600000
#define TM 128
#define NBLK ((N_NODES + TM - 1) / TM)
#define THREADS 512
#define NPERS 148     // persistent CTAs (~1 per SM)
#define LDK 136       // padded K stride (odd 16B stride -> conflict-free frag loads)
#define WBLK 64       // weight-image blocks inside prep_scatter

// ---- SMEM byte offsets (persistent layout: A + B1 + B2 resident together) ----
#define OFF_B1HI 0            // 34816 each  [128][136] bf16
#define OFF_B1LO 34816
#define OFF_B2HI 69632
#define OFF_B2LO 104448
#define OFF_AHI  139264
#define OFF_ALO  174080
#define OFF_MEA  208896       // [128][4] fp32
#define OFF_W1C  210944       // [3][128] fp32
#define OFF_B1   212480       // [128] fp32
#define OFF_B2   212992       // [128] fp32
#define OFF_ZB   213504       // [4] uint32 zero-degree ballots (+pad to 32)
#define OFF_FIX  213536       // [4][128] fp32 per-group fixup scratch
#define SMEM_TOTAL 215584

// ---- global scratch ----
// g_agg invariant: all-zero at launch start. First launch: static zero-init.
// Afterwards: fused_kernel consumes-and-clears every entry it reads, so each
// complete execution (and each graph replay) restores the invariant.
__device__ float4 g_agg[N_NODES];                      // sum_ea0..2, count
__device__ __align__(16) __nv_bfloat16 g_B1hi[128 * LDK];  // [n][k] = Wsum[k][n]
__device__ __align__(16) __nv_bfloat16 g_B1lo[128 * LDK];
__device__ __align__(16) __nv_bfloat16 g_B2hi[128 * LDK];  // [n][k] = W2[k][n]
__device__ __align__(16) __nv_bfloat16 g_B2lo[128 * LDK];

__device__ __forceinline__ uint32_t pack_bf(float a, float b) {
    __nv_bfloat162 t = __floats2bfloat162_rn(a, b);
    return *(uint32_t*)&t;
}
__device__ __forceinline__ float bf_resid(float v) {
    return v - __bfloat162float(__float2bfloat16_rn(v));
}
__device__ __forceinline__ void mma_bf16(float* c, const uint32_t* a, const uint32_t* b) {
    asm volatile(
        "mma.sync.aligned.m16n8k16.row.col.f32.bf16.bf16.f32 "
        "{%0,%1,%2,%3}, {%4,%5,%6,%7}, {%8,%9}, {%0,%1,%2,%3};"
        : "+f"(c[0]), "+f"(c[1]), "+f"(c[2]), "+f"(c[3])
        : "r"(a[0]), "r"(a[1]), "r"(a[2]), "r"(a[3]), "r"(b[0]), "r"(b[1]));
}
__device__ __forceinline__ void red_v4(float4* p, float a, float b, float c, float d) {
    asm volatile("red.global.add.v4.f32 [%0], {%1, %2, %3, %4};"
                 :: "l"(p), "f"(a), "f"(b), "f"(c), "f"(d) : "memory");
}
__device__ __forceinline__ void bar_grp(int id) {
    asm volatile("bar.sync %0, %1;" :: "r"(id), "r"(128) : "memory");
}

// ---------------------------------------------------------------------------
// prep_scatter: blocks [0,WBLK) build weight images; the rest scatter edges
// (4 edges/thread, vectorized loads, red.global.add.v4.f32).
// ---------------------------------------------------------------------------
__global__ void prep_scatter_kernel(const int* __restrict__ ei32,
                                    const float* __restrict__ ea,
                                    const float* __restrict__ W1,
                                    const float* __restrict__ W2) {
    int b = blockIdx.x;
    if (b < WBLK) {
        int tid = b * blockDim.x + threadIdx.x;
        int stride = WBLK * blockDim.x;
        for (int i = tid; i < 128 * 128; i += stride) {
            int n = i >> 7, k = i & 127;
            float v = W1[k * 128 + n] + W1[(128 + k) * 128 + n];   // Wsum^T
            __nv_bfloat16 h = __float2bfloat16_rn(v);
            g_B1hi[n * LDK + k] = h;
            g_B1lo[n * LDK + k] = __float2bfloat16_rn(v - __bfloat162float(h));
            float w = W2[k * 128 + n];                              // W2^T
            __nv_bfloat16 h2 = __float2bfloat16_rn(w);
            g_B2hi[n * LDK + k] = h2;
            g_B2lo[n * LDK + k] = __float2bfloat16_rn(w - __bfloat162float(h2));
        }
        for (int i = tid; i < 128 * (LDK - 128); i += stride) {
            int n = i / (LDK - 128), k = 128 + i % (LDK - 128);
            g_B1hi[n * LDK + k] = __float2bfloat16_rn(0.f);
            g_B1lo[n * LDK + k] = __float2bfloat16_rn(0.f);
            g_B2hi[n * LDK + k] = __float2bfloat16_rn(0.f);
            g_B2lo[n * LDK + k] = __float2bfloat16_rn(0.f);
        }
        return;
    }
    int e0 = ((b - WBLK) * blockDim.x + threadIdx.x) * 4;
    if (e0 >= N_EDGES) return;   // N_EDGES % 4 == 0
    // int64 vs int32 edge_index detection (L1-broadcast loads, ~free)
    int idx64 = ((ei32[1] | ei32[3] | ei32[5] | ei32[7]) == 0);
    int s0, s1, s2, s3;
    if (idx64) {
        const int4* p = (const int4*)(ei32 + 2 * (N_EDGES + e0));
        int4 a = p[0], c = p[1];
        s0 = a.x; s1 = a.z; s2 = c.x; s3 = c.z;   // low words of 4 int64
    } else {
        int4 a = *(const int4*)(ei32 + N_EDGES + e0);
        s0 = a.x; s1 = a.y; s2 = a.z; s3 = a.w;
    }
    const float4* q = (const float4*)(ea + (size_t)e0 * 3);
    float4 q0 = q[0], q1 = q[1], q2 = q[2];
    red_v4(&g_agg[s0], q0.x, q0.y, q0.z, 1.0f);
    red_v4(&g_agg[s1], q0.w, q1.x, q1.y, 1.0f);
    red_v4(&g_agg[s2], q1.z, q1.w, q2.x, 1.0f);
    red_v4(&g_agg[s3], q2.y, q2.z, q2.w, 1.0f);
}

// ---------------------------------------------------------------------------
// fused (persistent, 512 thr): four decoupled 32-row group pipelines per CTA.
// Group g = warps {g, g+4, g+8, g+12}; all intra-tile syncs are group-scoped
// named barriers, so groups overlap DRAM loads with other groups' MMA.
// ---------------------------------------------------------------------------
__global__ __launch_bounds__(THREADS, 1)
void fused_kernel(const float* __restrict__ x,
                  const float* __restrict__ W1,
                  const float* __restrict__ b1g,
                  const float* __restrict__ W2,
                  const float* __restrict__ b2g,
                  float* __restrict__ out) {
    extern __shared__ char smem[];
    __nv_bfloat16* sB1hi = (__nv_bfloat16*)(smem + OFF_B1HI);
    __nv_bfloat16* sB1lo = (__nv_bfloat16*)(smem + OFF_B1LO);
    __nv_bfloat16* sB2hi = (__nv_bfloat16*)(smem + OFF_B2HI);
    __nv_bfloat16* sB2lo = (__nv_bfloat16*)(smem + OFF_B2LO);
    __nv_bfloat16* sAhi  = (__nv_bfloat16*)(smem + OFF_AHI);
    __nv_bfloat16* sAlo  = (__nv_bfloat16*)(smem + OFF_ALO);
    float* sMea = (float*)(smem + OFF_MEA);
    float* sW1c = (float*)(smem + OFF_W1C);
    float* sB1  = (float*)(smem + OFF_B1);
    float* sB2  = (float*)(smem + OFF_B2);
    unsigned* sZb = (unsigned*)(smem + OFF_ZB);
    float* sFix = (float*)(smem + OFF_FIX);

    const int tid = threadIdx.x, wid = tid >> 5, lane = tid & 31;
    const int gID = lane >> 2, tIG = lane & 3;
    const int grp = wid & 3;            // row group 0..3
    const int gtid = (wid >> 2) * 32 + lane;   // 0..127 within group
    const int barid = 1 + grp;
    const int wr = grp * 32;            // warp row base
    const int wc = (wid >> 2) * 32;     // warp col base

    // ---- one-time: biases, W1c, all 4 weight images ----
    if (tid < 128) { sB1[tid] = b1g[tid]; sB2[tid] = b2g[tid]; }
    for (int i = tid; i < 3 * 128; i += THREADS) sW1c[i] = W1[256 * 128 + i];
    {
        const uint4* s1 = (const uint4*)g_B1hi;
        const uint4* s2 = (const uint4*)g_B1lo;
        const uint4* s3 = (const uint4*)g_B2hi;
        const uint4* s4 = (const uint4*)g_B2lo;
        uint4* d1 = (uint4*)sB1hi;
        uint4* d2 = (uint4*)sB1lo;
        uint4* d3 = (uint4*)sB2hi;
        uint4* d4 = (uint4*)sB2lo;
        for (int i = tid; i < 128 * LDK * 2 / 16; i += THREADS) {
            d1[i] = s1[i]; d2[i] = s2[i]; d3[i] = s3[i]; d4[i] = s4[i];
        }
    }
    __syncthreads();

#define MMA_LAYER(SBH, SBL)                                                     \
    _Pragma("unroll")                                                           \
    for (int ks = 0; ks < 8; ks++) {                                            \
        const int k0 = ks * 16 + tIG * 2;                                       \
        uint32_t aH[2][4], aL[2][4], bH[4][2], bL[4][2];                        \
        _Pragma("unroll")                                                       \
        for (int ma = 0; ma < 2; ma++) {                                        \
            int r = wr + ma * 16 + gID;                                         \
            aH[ma][0] = *(const uint32_t*)(sAhi + r * LDK + k0);                \
            aH[ma][1] = *(const uint32_t*)(sAhi + (r + 8) * LDK + k0);          \
            aH[ma][2] = *(const uint32_t*)(sAhi + r * LDK + k0 + 8);            \
            aH[ma][3] = *(const uint32_t*)(sAhi + (r + 8) * LDK + k0 + 8);      \
            aL[ma][0] = *(const uint32_t*)(sAlo + r * LDK + k0);                \
            aL[ma][1] = *(const uint32_t*)(sAlo + (r + 8) * LDK + k0);          \
            aL[ma][2] = *(const uint32_t*)(sAlo + r * LDK + k0 + 8);            \
            aL[ma][3] = *(const uint32_t*)(sAlo + (r + 8) * LDK + k0 + 8);      \
        }                                                                       \
        _Pragma("unroll")                                                       \
        for (int na = 0; na < 4; na++) {                                        \
            int n = wc + na * 8 + gID;                                          \
            bH[na][0] = *(const uint32_t*)((SBH) + n * LDK + k0);               \
            bH[na][1] = *(const uint32_t*)((SBH) + n * LDK + k0 + 8);           \
            bL[na][0] = *(const uint32_t*)((SBL) + n * LDK + k0);               \
            bL[na][1] = *(const uint32_t*)((SBL) + n * LDK + k0 + 8);           \
        }                                                                       \
        _Pragma("unroll")                                                       \
        for (int ma = 0; ma < 2; ma++)                                          \
            _Pragma("unroll")                                                   \
            for (int na = 0; na < 4; na++) {                                    \
                mma_bf16(acc[ma][na], aH[ma], bH[na]);                          \
                mma_bf16(acc[ma][na], aL[ma], bH[na]);                          \
                mma_bf16(acc[ma][na], aH[ma], bL[na]);                          \
            }                                                                   \
    }

    for (int t = blockIdx.x; t < NBLK; t += gridDim.x) {
        const int node0 = t * TM;
        // protect own group's sA (prev MMA2 reads) + sZb/sMea before rewrite
        bar_grp(barid);

        // ---- mea + zero-degree ballot + consume-and-clear (warp g = group g rows) ----
        if (wid < 4) {
            int g = node0 + wid * 32 + lane;
            float4 a = make_float4(0.f, 0.f, 0.f, 1.f);
            if (g < N_NODES) {
                a = g_agg[g];
                g_agg[g] = make_float4(0.f, 0.f, 0.f, 0.f);   // restore invariant
            }
            unsigned zb = __ballot_sync(0xffffffffu, (g < N_NODES) && (a.w == 0.f));
            if (lane == 0) sZb[wid] = zb;
            float inv = 1.0f / fmaxf(a.w, 1.0f);
            int rr = wid * 32 + lane;
            sMea[rr * 4 + 0] = a.x * inv;
            sMea[rr * 4 + 1] = a.y * inv;
            sMea[rr * 4 + 2] = a.z * inv;
        }

        // ---- x -> sA hi/lo (own 32 rows only) ----
        const float4* x4 = (const float4*)x;
        for (int idx = gtid; idx < 32 * 32; idx += 128) {
            int rl = idx >> 5, kq = idx & 31;
            int r = wr + rl, g = node0 + r;
            float4 v = make_float4(0.f, 0.f, 0.f, 0.f);
            if (g < N_NODES) v = x4[(size_t)g * 32 + kq];
            int o = r * LDK + kq * 4;
            *(uint32_t*)(sAhi + o)     = pack_bf(v.x, v.y);
            *(uint32_t*)(sAhi + o + 2) = pack_bf(v.z, v.w);
            *(uint32_t*)(sAlo + o)     = pack_bf(bf_resid(v.x), bf_resid(v.y));
            *(uint32_t*)(sAlo + o + 2) = pack_bf(bf_resid(v.z), bf_resid(v.w));
        }
        bar_grp(barid);

        float acc[2][4][4];
#pragma unroll
        for (int ma = 0; ma < 2; ma++)
#pragma unroll
            for (int na = 0; na < 4; na++)
#pragma unroll
                for (int c = 0; c < 4; c++) acc[ma][na][c] = 0.f;

        MMA_LAYER(sB1hi, sB1lo)
        bar_grp(barid);   // group's A reads done before epilogue1 overwrites

        // ---- epilogue1: h = relu(acc + b1 + mea@W1c) -> sA hi/lo; reset acc ----
#pragma unroll
        for (int ma = 0; ma < 2; ma++) {
            int r0 = wr + ma * 16 + gID;
            float m00 = sMea[r0 * 4], m01 = sMea[r0 * 4 + 1], m02 = sMea[r0 * 4 + 2];
            int r1 = r0 + 8;
            float m10 = sMea[r1 * 4], m11 = sMea[r1 * 4 + 1], m12 = sMea[r1 * 4 + 2];
#pragma unroll
            for (int na = 0; na < 4; na++) {
                int c0 = wc + na * 8 + tIG * 2;
                float e0 = sB1[c0]     + m00 * sW1c[c0]     + m01 * sW1c[128 + c0]     + m02 * sW1c[256 + c0];
                float e1 = sB1[c0 + 1] + m00 * sW1c[c0 + 1] + m01 * sW1c[128 + c0 + 1] + m02 * sW1c[256 + c0 + 1];
                float f0 = sB1[c0]     + m10 * sW1c[c0]     + m11 * sW1c[128 + c0]     + m12 * sW1c[256 + c0];
                float f1 = sB1[c0 + 1] + m10 * sW1c[c0 + 1] + m11 * sW1c[128 + c0 + 1] + m12 * sW1c[256 + c0 + 1];
                float v0 = fmaxf(acc[ma][na][0] + e0, 0.f);
                float v1 = fmaxf(acc[ma][na][1] + e1, 0.f);
                float v2 = fmaxf(acc[ma][na][2] + f0, 0.f);
                float v3 = fmaxf(acc[ma][na][3] + f1, 0.f);
                *(uint32_t*)(sAhi + r0 * LDK + c0) = pack_bf(v0, v1);
                *(uint32_t*)(sAlo + r0 * LDK + c0) = pack_bf(bf_resid(v0), bf_resid(v1));
                *(uint32_t*)(sAhi + r1 * LDK + c0) = pack_bf(v2, v3);
                *(uint32_t*)(sAlo + r1 * LDK + c0) = pack_bf(bf_resid(v2), bf_resid(v3));
#pragma unroll
                for (int c = 0; c < 4; c++) acc[ma][na][c] = 0.f;
            }
        }
        bar_grp(barid);

        MMA_LAYER(sB2hi, sB2lo)

        // ---- epilogue2: out = acc + b2 (direct global stores, 8B each) ----
#pragma unroll
        for (int ma = 0; ma < 2; ma++) {
            int r0 = wr + ma * 16 + gID;
            int g0 = node0 + r0, g1 = g0 + 8;
#pragma unroll
            for (int na = 0; na < 4; na++) {
                int c0 = wc + na * 8 + tIG * 2;
                if (g0 < N_NODES) {
                    float2 v = make_float2(acc[ma][na][0] + sB2[c0], acc[ma][na][1] + sB2[c0 + 1]);
                    *(float2*)(out + (size_t)g0 * 128 + c0) = v;
                }
                if (g1 < N_NODES) {
                    float2 v = make_float2(acc[ma][na][2] + sB2[c0], acc[ma][na][3] + sB2[c0 + 1]);
                    *(float2*)(out + (size_t)g1 * 128 + c0) = v;
                }
            }
        }

        // ---- group-local fixup: exact fp32 recompute for zero-degree nodes ----
        {
            unsigned m = sZb[grp];   // written by warp grp this tile (ordered by bars)
            if (m) {
                float* fx = sFix + grp * 128;
                while (m) {
                    int b = __ffs(m) - 1;
                    m &= m - 1;
                    int n = node0 + wr + b;
                    float a1 = sB1[gtid];
                    for (int k = 0; k < 128; k++)
                        a1 = fmaf(x[(size_t)n * 128 + k], W1[k * 128 + gtid], a1);
                    fx[gtid] = fmaxf(a1, 0.f);
                    bar_grp(barid);
                    float a2 = sB2[gtid];
                    for (int k = 0; k < 128; k++)
                        a2 = fmaf(fx[k], W2[k * 128 + gtid], a2);
                    out[(size_t)n * 128 + gtid] = a2;
                    bar_grp(barid);
                }
            }
        }
    }
#undef MMA_LAYER
}

// ---------------------------------------------------------------------------
extern "C" void kernel_launch(void* const* d_in, const int* in_sizes, int n_in,
                              void* d_out, int out_size) {
    const float* x    = (const float*)d_in[0];
    const int*   ei32 = (const int*)d_in[1];
    const float* ea   = (const float*)d_in[2];
    const float* W1   = (const float*)d_in[5];
    const float* b1   = (const float*)d_in[6];
    const float* W2   = (const float*)d_in[7];
    const float* b2   = (const float*)d_in[8];
    float* out = (float*)d_out;

    cudaFuncSetAttribute(fused_kernel, cudaFuncAttributeMaxDynamicSharedMemorySize, SMEM_TOTAL);

    int eblk = (N_EDGES / 4 + 255) / 256;
    prep_scatter_kernel<<<WBLK + eblk, 256>>>(ei32, ea, W1, W2);
    fused_kernel<<<NPERS, THREADS, SMEM_TOTAL>>>(x, W1, b1, W2, b2, out);
}